// round 4
// baseline (speedup 1.0000x reference)
#include <cuda_runtime.h>
#include <math.h>

// Fixed problem shape (GCN_ten): N=200000, E=6400000, F=128, H=16, C=40, 8 hidden layers.
#define MAXN 200704
#define MAXE 6500352
#define HDIM 16

// Scratch (static __device__ arrays — no allocation allowed)
__device__ int    d_counts[MAXN];
__device__ int    d_rowoff[MAXN + 1];
__device__ int    d_cursor[MAXN];
__device__ float  d_dis[MAXN];
__device__ int    d_csr[MAXE];
__device__ float4 d_gA[(size_t)MAXN * 4];   // node table, 64B/row, float4-aligned
__device__ float4 d_gB[(size_t)MAXN * 4];
__device__ int    d_is64;

// ---------------------------------------------------------------------------
// Launch 0: zero the degree histogram + detect int64 vs int32 edge_index.
// (int64 little-endian with ids < 2^31 -> odd 32-bit words all zero.)
__global__ void init_kernel(const unsigned int* __restrict__ p, int nwords, int n) {
    int i = blockIdx.x * blockDim.x + threadIdx.x;
    if (i < n) d_counts[i] = 0;
    if (i == 0) {
        int flag = 1;
        int lim = min(64, nwords);
        for (int k = 1; k < lim; k += 2)
            if (p[k] != 0u) flag = 0;
        d_is64 = flag;
    }
}

// Launch 1: degree histogram over dst.
__global__ void count_edges(const void* __restrict__ eidx, int E) {
    int i = blockIdx.x * blockDim.x + threadIdx.x;
    if (i >= E) return;
    int d;
    if (d_is64) d = (int)((const long long*)eidx)[(size_t)E + i];
    else        d = ((const int*)eidx)[E + i];
    atomicAdd(&d_counts[d], 1);
}

// Launch 2: fused dis = rsqrt(deg+1) + single-block exclusive scan -> rowoff/cursor.
__global__ void scan_dis_kernel(int n) {
    __shared__ int sums[1024];
    int tid = threadIdx.x;
    int chunk = (n + 1023) >> 10;
    int start = min(tid * chunk, n);
    int end   = min(start + chunk, n);
    int s = 0;
    for (int i = start; i < end; i++) {
        int c = d_counts[i];
        d_dis[i] = rsqrtf((float)(c + 1));   // +1 self loop
        s += c;
    }
    sums[tid] = s;
    __syncthreads();
    for (int off = 1; off < 1024; off <<= 1) {
        int t = (tid >= off) ? sums[tid - off] : 0;
        __syncthreads();
        sums[tid] += t;
        __syncthreads();
    }
    int run = sums[tid] - s;
    for (int i = start; i < end; i++) {
        d_rowoff[i] = run;
        d_cursor[i] = run;
        run += d_counts[i];
    }
    if (tid == 1023) d_rowoff[n] = sums[1023];
}

// Launch 3: scatter src ids into CSR by dst.
__global__ void scatter_edges(const void* __restrict__ eidx, int E) {
    int i = blockIdx.x * blockDim.x + threadIdx.x;
    if (i >= E) return;
    int s, d;
    if (d_is64) {
        const long long* p = (const long long*)eidx;
        s = (int)p[i];
        d = (int)p[(size_t)E + i];
    } else {
        const int* p = (const int*)eidx;
        s = p[i];
        d = p[E + i];
    }
    int pos = atomicAdd(&d_cursor[d], 1);
    d_csr[pos] = s;
}

// ---------------------------------------------------------------------------
// Launch 4: g0[v] = dis[v] * (x[v] @ w_in).  16 threads per node.
__global__ void in_proj(const float* __restrict__ x,
                        const float* __restrict__ w, int n, int F) {
    __shared__ float Wsh[128 * HDIM];
    for (int t = threadIdx.x; t < F * HDIM; t += blockDim.x) Wsh[t] = w[t];
    __syncthreads();
    int g = blockIdx.x * blockDim.x + threadIdx.x;
    int v = g >> 4, j = g & 15;
    if (v >= n) return;
    const float4* xr = (const float4*)(x + (size_t)v * F);
    float acc = 0.f;
#pragma unroll 8
    for (int q = 0; q < 32; q++) {
        float4 xv = __ldg(&xr[q]);
        int f4 = q * 4;
        acc = fmaf(xv.x, Wsh[(f4 + 0) * HDIM + j], acc);
        acc = fmaf(xv.y, Wsh[(f4 + 1) * HDIM + j], acc);
        acc = fmaf(xv.z, Wsh[(f4 + 2) * HDIM + j], acc);
        acc = fmaf(xv.w, Wsh[(f4 + 3) * HDIM + j], acc);
    }
    ((float*)d_gA)[(size_t)v * HDIM + j] = acc * d_dis[v];
}

// ---------------------------------------------------------------------------
// Warp-per-node fused layer: agg(g_in) -> *dis -> (@W) -> +b -> relu -> *dis.
// Lane = slot(0..7)*4 + chunk(0..3): 8 edge slots x float4 row chunks.
// W == nullptr: identity (layer 1, matmul already applied by in_proj).
__global__ void __launch_bounds__(256) agg_layer(const float* __restrict__ W,
                                                 const float* __restrict__ bias,
                                                 int sel, int n) {
    __shared__ float Wsh[HDIM * HDIM];
    __shared__ float bsh[HDIM];
    const float4* __restrict__ gin = sel ? d_gB : d_gA;
    float* __restrict__        gout = (float*)(sel ? d_gA : d_gB);
    int tid = threadIdx.x;
    if (W != nullptr && tid < HDIM * HDIM) Wsh[tid] = W[tid];
    if (tid < HDIM) bsh[tid] = bias[tid];
    __syncthreads();

    int v = (blockIdx.x * blockDim.x + tid) >> 5;
    if (v >= n) return;                       // uniform per warp
    int lane  = tid & 31;
    int slot  = lane >> 2;
    int chunk = lane & 3;

    float dv = d_dis[v];
    int s = d_rowoff[v], e = d_rowoff[v + 1];
    float4 acc = make_float4(0.f, 0.f, 0.f, 0.f);
    int i = s;
    for (; i + 16 <= e; i += 16) {            // 16 edges in flight per warp
        int u0 = __ldg(&d_csr[i + slot]);
        int u1 = __ldg(&d_csr[i + 8 + slot]);
        float4 x0 = __ldg(&gin[(size_t)u0 * 4 + chunk]);
        float4 x1 = __ldg(&gin[(size_t)u1 * 4 + chunk]);
        acc.x += x0.x + x1.x; acc.y += x0.y + x1.y;
        acc.z += x0.z + x1.z; acc.w += x0.w + x1.w;
    }
    for (; i < e; i += 8) {
        int j = i + slot;
        if (j < e) {
            int u = __ldg(&d_csr[j]);
            float4 x0 = __ldg(&gin[(size_t)u * 4 + chunk]);
            acc.x += x0.x; acc.y += x0.y; acc.z += x0.z; acc.w += x0.w;
        }
    }
    // reduce over the 8 edge slots (lane bits 2,3,4)
#pragma unroll
    for (int off = 4; off <= 16; off <<= 1) {
        acc.x += __shfl_xor_sync(0xffffffffu, acc.x, off);
        acc.y += __shfl_xor_sync(0xffffffffu, acc.y, off);
        acc.z += __shfl_xor_sync(0xffffffffu, acc.z, off);
        acc.w += __shfl_xor_sync(0xffffffffu, acc.w, off);
    }
    // self loop + scale: a = dv * (sum + g[v]); lane holds features 4*chunk..4*chunk+3
    float4 sl = __ldg(&gin[(size_t)v * 4 + chunk]);
    acc.x = (acc.x + sl.x) * dv; acc.y = (acc.y + sl.y) * dv;
    acc.z = (acc.z + sl.z) * dv; acc.w = (acc.w + sl.w) * dv;

    int f = lane & 15;
    float h;
    if (W != nullptr) {
        h = 0.f;
#pragma unroll
        for (int k = 0; k < HDIM; k++) {       // src lane & component compile-time
            float comp = ((k & 3) == 0) ? acc.x : ((k & 3) == 1) ? acc.y
                       : ((k & 3) == 2) ? acc.z : acc.w;
            float ak = __shfl_sync(0xffffffffu, comp, k >> 2);
            h = fmaf(ak, Wsh[k * HDIM + f], h);
        }
    } else {
        int src = (lane >> 2) & 3;             // lane holding chunk f>>2
        float cx = __shfl_sync(0xffffffffu, acc.x, src);
        float cy = __shfl_sync(0xffffffffu, acc.y, src);
        float cz = __shfl_sync(0xffffffffu, acc.z, src);
        float cw = __shfl_sync(0xffffffffu, acc.w, src);
        int c = lane & 3;
        h = (c == 0) ? cx : (c == 1) ? cy : (c == 2) ? cz : cw;
    }

    if (lane < 16) {
        h = fmaxf(h + bsh[f], 0.f);
        gout[(size_t)v * HDIM + f] = h * dv;
    }
}

// ---------------------------------------------------------------------------
// Final layer (warp-per-node): agg -> *dis -> @w_out(16xC)+b -> log_softmax.
__global__ void __launch_bounds__(256) final_layer(const float* __restrict__ W,
                                                   const float* __restrict__ bias,
                                                   int sel, int n, int C,
                                                   float* __restrict__ out) {
    __shared__ float Wsh[HDIM * 48];
    __shared__ float bsh[48];
    const float4* __restrict__ gin = sel ? d_gB : d_gA;
    int tid = threadIdx.x;
    for (int t = tid; t < HDIM * C; t += blockDim.x) Wsh[t] = W[t];
    for (int t = tid; t < C; t += blockDim.x) bsh[t] = bias[t];
    __syncthreads();

    int v = (blockIdx.x * blockDim.x + tid) >> 5;
    if (v >= n) return;
    int lane  = tid & 31;
    int slot  = lane >> 2;
    int chunk = lane & 3;

    float dv = d_dis[v];
    int s = d_rowoff[v], e = d_rowoff[v + 1];
    float4 acc = make_float4(0.f, 0.f, 0.f, 0.f);
    int i = s;
    for (; i + 16 <= e; i += 16) {
        int u0 = __ldg(&d_csr[i + slot]);
        int u1 = __ldg(&d_csr[i + 8 + slot]);
        float4 x0 = __ldg(&gin[(size_t)u0 * 4 + chunk]);
        float4 x1 = __ldg(&gin[(size_t)u1 * 4 + chunk]);
        acc.x += x0.x + x1.x; acc.y += x0.y + x1.y;
        acc.z += x0.z + x1.z; acc.w += x0.w + x1.w;
    }
    for (; i < e; i += 8) {
        int j = i + slot;
        if (j < e) {
            int u = __ldg(&d_csr[j]);
            float4 x0 = __ldg(&gin[(size_t)u * 4 + chunk]);
            acc.x += x0.x; acc.y += x0.y; acc.z += x0.z; acc.w += x0.w;
        }
    }
#pragma unroll
    for (int off = 4; off <= 16; off <<= 1) {
        acc.x += __shfl_xor_sync(0xffffffffu, acc.x, off);
        acc.y += __shfl_xor_sync(0xffffffffu, acc.y, off);
        acc.z += __shfl_xor_sync(0xffffffffu, acc.z, off);
        acc.w += __shfl_xor_sync(0xffffffffu, acc.w, off);
    }
    float4 sl = __ldg(&gin[(size_t)v * 4 + chunk]);
    acc.x = (acc.x + sl.x) * dv; acc.y = (acc.y + sl.y) * dv;
    acc.z = (acc.z + sl.z) * dv; acc.w = (acc.w + sl.w) * dv;

    // logits: lane -> col lane, and col lane+32 (valid when lane+32 < C)
    int j0 = lane, j1 = lane + 32;
    float z0 = (j0 < C) ? bsh[j0] : -INFINITY;
    float z1 = (j1 < C) ? bsh[j1] : -INFINITY;
#pragma unroll
    for (int k = 0; k < HDIM; k++) {
        float comp = ((k & 3) == 0) ? acc.x : ((k & 3) == 1) ? acc.y
                   : ((k & 3) == 2) ? acc.z : acc.w;
        float ak = __shfl_sync(0xffffffffu, comp, k >> 2);
        if (j0 < C) z0 = fmaf(ak, Wsh[k * C + j0], z0);
        if (j1 < C) z1 = fmaf(ak, Wsh[k * C + j1], z1);
    }

    float m = fmaxf(z0, z1);
#pragma unroll
    for (int o = 16; o; o >>= 1) m = fmaxf(m, __shfl_xor_sync(0xffffffffu, m, o));
    float ssum = ((j0 < C) ? expf(z0 - m) : 0.f) + ((j1 < C) ? expf(z1 - m) : 0.f);
#pragma unroll
    for (int o = 16; o; o >>= 1) ssum += __shfl_xor_sync(0xffffffffu, ssum, o);
    float l = m + logf(ssum);

    size_t rb = (size_t)v * C;
    if (j0 < C) out[rb + j0] = z0 - l;
    if (j1 < C) out[rb + j1] = z1 - l;
}

// ---------------------------------------------------------------------------
extern "C" void kernel_launch(void* const* d_in, const int* in_sizes, int n_in,
                              void* d_out, int out_size) {
    const float* x     = (const float*)d_in[0];
    const float* w_in  = (const float*)d_in[1];
    const float* b_in  = (const float*)d_in[2];
    const float* w_hid = (const float*)d_in[3];
    const float* b_hid = (const float*)d_in[4];
    const float* w_out = (const float*)d_in[5];
    const float* b_out = (const float*)d_in[6];
    const void*  eidx  = d_in[7];
    float* out = (float*)d_out;

    const int H = in_sizes[2];           // 16
    const int F = in_sizes[1] / H;       // 128
    const int N = in_sizes[0] / F;       // 200000
    const int C = in_sizes[6];           // 40
    const int L = in_sizes[4] / H;       // 8 hidden layers
    const int E = in_sizes[7] / 2;       // 6400000

    const int TB = 256;
    // Launches 0-3: preprocessing (CSR build, dis)
    init_kernel<<<(N + TB - 1) / TB, TB>>>((const unsigned int*)eidx, E * 2, N);
    count_edges<<<(E + TB - 1) / TB, TB>>>(eidx, E);
    scan_dis_kernel<<<1, 1024>>>(N);
    scatter_edges<<<(E + TB - 1) / TB, TB>>>(eidx, E);

    // Launch 4: input projection (128 -> 16)
    in_proj<<<((N * 16) + TB - 1) / TB, TB>>>(x, w_in, N, F);

    int aggBlocks = (N * 32 + TB - 1) / TB;  // warp per node

    // Launch 5 (ncu-profiled): layer 1, identity-W
    agg_layer<<<aggBlocks, TB>>>(nullptr, b_in, /*sel=*/0, N);
    int sel = 1;
    for (int i = 0; i < L; i++) {
        agg_layer<<<aggBlocks, TB>>>(w_hid + (size_t)i * H * H,
                                     b_hid + (size_t)i * H, sel, N);
        sel ^= 1;
    }
    final_layer<<<aggBlocks, TB>>>(w_out, b_out, sel, N, C, out);
}